// round 2
// baseline (speedup 1.0000x reference)
#include <cuda_runtime.h>
#include <math.h>

#define T_   8192
#define DIN  2048
#define D_   512
#define H_   512
#define H3_  1536
#define A_   18

#define NC   64          // recurrence CTAs (single wave: 64 < 148 SMs)
#define HC   (H_/NC)     // 8 hidden units per CTA (one warp each)

// ---------------- scratch (device globals: no allocation allowed) ----------
__device__ float g_z1[(size_t)T_ * D_];          // 16 MB
__device__ float g_z2[(size_t)T_ * D_];          // 16 MB
__device__ float g_X [(size_t)T_ * H3_];         // 48 MB
__device__ float g_seq[(size_t)T_ * H_];         // 16 MB
__device__ unsigned long long g_hbuf[2 * H_];    // tagged double-buffered h

// ---------------- relaxed gpu-scope 64-bit ld/st for the spin protocol -----
__device__ __forceinline__ unsigned long long ld_relaxed_u64(const unsigned long long* p) {
    unsigned long long v;
    asm volatile("ld.relaxed.gpu.global.u64 %0, [%1];" : "=l"(v) : "l"(p) : "memory");
    return v;
}
__device__ __forceinline__ void st_relaxed_u64(unsigned long long* p, unsigned long long v) {
    asm volatile("st.relaxed.gpu.global.u64 [%0], %1;" :: "l"(p), "l"(v) : "memory");
}

// ---------------- init: reset tagged h buffers every replay ----------------
__global__ void init_kernel(const float* __restrict__ h0) {
    int i = blockIdx.x * blockDim.x + threadIdx.x;
    if (i < H_) {
        // buf0: sentinel tag (never matches any expected tag 0..8192)
        g_hbuf[i] = 0xFFFFFFFFull;
        // buf1: h_{-1} with tag 0
        g_hbuf[H_ + i] = ((unsigned long long)__float_as_uint(h0[i]) << 32);
    }
}

// ---------------- fp32 tiled GEMM: C = act(A[M,K] @ B[K,N] + bias) ---------
__global__ __launch_bounds__(256) void gemm_kernel(
    const float* __restrict__ A, const float* __restrict__ B,
    const float* __restrict__ bias, float* __restrict__ C,
    int M, int N, int K, int doRelu)
{
    __shared__ float As[16][64];
    __shared__ float Bs[16][64];
    const int tid = threadIdx.x;
    const int bm = blockIdx.y * 64;
    const int bn = blockIdx.x * 64;
    const int tx = tid & 15, ty = tid >> 4;

    const int aRow = tid >> 2;            // 0..63
    const int aK   = (tid & 3) << 2;      // 0,4,8,12
    const int bRow = tid >> 4;            // 0..15
    const int bCol = (tid & 15) << 2;     // 0..60

    const float* Aptr = A + (size_t)(bm + aRow) * K + aK;
    const float* Bptr = B + (size_t)bRow * N + bn + bCol;

    float acc[4][4];
#pragma unroll
    for (int i = 0; i < 4; i++)
#pragma unroll
        for (int j = 0; j < 4; j++) acc[i][j] = 0.f;

    for (int k0 = 0; k0 < K; k0 += 16) {
        float4 a4 = *(const float4*)(Aptr + k0);
        float4 b4 = *(const float4*)(Bptr + (size_t)k0 * N);
        As[aK + 0][aRow] = a4.x;
        As[aK + 1][aRow] = a4.y;
        As[aK + 2][aRow] = a4.z;
        As[aK + 3][aRow] = a4.w;
        *(float4*)&Bs[bRow][bCol] = b4;
        __syncthreads();
#pragma unroll
        for (int k = 0; k < 16; k++) {
            float4 av = *(const float4*)&As[k][ty << 2];
            float4 bv = *(const float4*)&Bs[k][tx << 2];
            float a_[4] = {av.x, av.y, av.z, av.w};
            float b_[4] = {bv.x, bv.y, bv.z, bv.w};
#pragma unroll
            for (int i = 0; i < 4; i++)
#pragma unroll
                for (int j = 0; j < 4; j++)
                    acc[i][j] = fmaf(a_[i], b_[j], acc[i][j]);
        }
        __syncthreads();
    }

#pragma unroll
    for (int i = 0; i < 4; i++) {
        int m = bm + (ty << 2) + i;
#pragma unroll
        for (int j = 0; j < 4; j++) {
            int n = bn + (tx << 2) + j;
            float v = acc[i][j] + bias[n];
            if (doRelu) v = fmaxf(v, 0.f);
            C[(size_t)m * N + n] = v;
        }
    }
}

// ---------------- GRU recurrence: 64 persistent CTAs, tagged spin-sync -----
__global__ __launch_bounds__(256) void recur_kernel(
    const float* __restrict__ Ug,    // [H, 3H] row-major
    const float* __restrict__ brec,  // [3H]  (bg row 1)
    const float* __restrict__ X,     // [T, 3H]
    float* __restrict__ seq,         // [T, H]
    float* __restrict__ hT_out)      // [H]
{
    __shared__ float sh[2][H_];
    const int tid  = threadIdx.x;
    const int lane = tid & 31;
    const int w    = tid >> 5;                 // warp 0..7
    const int j    = blockIdx.x * HC + w;      // hidden unit owned by this warp

    // Stage this warp's Ug columns into registers: lane covers k = lane+32*kk
    float wz[16], wr[16], wh[16];
#pragma unroll
    for (int kk = 0; kk < 16; kk++) {
        const float* row = Ug + (size_t)(lane + (kk << 5)) * H3_;
        wz[kk] = row[j];
        wr[kk] = row[j + H_];
        wh[kk] = row[j + 2 * H_];
    }
    const float bz = brec[j], br = brec[j + H_], bh = brec[j + 2 * H_];

    // lane 0 holds the X row values for this unit (prefetched)
    float xz = 0.f, xr = 0.f, xh = 0.f;
    if (lane == 0) { xz = X[j]; xr = X[j + H_]; xh = X[j + 2 * H_]; }

    const int idx0 = tid, idx1 = tid + 256;

    for (int t = 0; t < T_; t++) {
        const int p = t & 1;
        const unsigned long long* rb = g_hbuf + (((t - 1) & 1) ? H_ : 0);
        const unsigned tag = (unsigned)t;

        // poll h_{t-1} (value+tag packed: no separate flag, no fence needed)
        unsigned long long v0 = 0, v1 = 0;
        bool d0 = false, d1 = false;
        do {
            if (!d0) { v0 = ld_relaxed_u64(rb + idx0); d0 = ((unsigned)v0 == tag); }
            if (!d1) { v1 = ld_relaxed_u64(rb + idx1); d1 = ((unsigned)v1 == tag); }
        } while (!(d0 && d1));
        sh[p][idx0] = __uint_as_float((unsigned)(v0 >> 32));
        sh[p][idx1] = __uint_as_float((unsigned)(v1 >> 32));
        __syncthreads();

        // rec dot products: 3 gates, 16 k's per lane
        float az = 0.f, ar = 0.f, ah = 0.f;
#pragma unroll
        for (int kk = 0; kk < 16; kk++) {
            float hv = sh[p][lane + (kk << 5)];
            az = fmaf(hv, wz[kk], az);
            ar = fmaf(hv, wr[kk], ar);
            ah = fmaf(hv, wh[kk], ah);
        }
#pragma unroll
        for (int off = 16; off; off >>= 1) {
            az += __shfl_xor_sync(0xffffffffu, az, off);
            ar += __shfl_xor_sync(0xffffffffu, ar, off);
            ah += __shfl_xor_sync(0xffffffffu, ah, off);
        }

        if (lane == 0) {
            float zt = 1.f / (1.f + __expf(-(xz + az + bz)));
            float rt = 1.f / (1.f + __expf(-(xr + ar + br)));
            float hh = 1.f / (1.f + __expf(-(xh + rt * (ah + bh))));
            float hp = sh[p][j];
            float hn = fmaf(zt, hp - hh, hh);   // zt*hp + (1-zt)*hh
            seq[(size_t)t * H_ + j] = hn;
            unsigned long long pk =
                ((unsigned long long)__float_as_uint(hn) << 32) | (unsigned)(t + 1);
            st_relaxed_u64(g_hbuf + (p ? H_ : 0) + j, pk);
            if (t == T_ - 1) hT_out[j] = hn;
            if (t + 1 < T_) {   // prefetch next X row (hidden under next poll)
                const float* xp = X + (size_t)(t + 1) * H3_;
                xz = __ldg(xp + j); xr = __ldg(xp + j + H_); xh = __ldg(xp + j + 2 * H_);
            }
        }
        // no 2nd barrier: sh is parity double-buffered and a warp cannot get
        // 2 steps ahead (it needs all of h_t, which needs this CTA's warps).
    }
}

// ---------------- heads: softmax policy (18) + value, one warp per row -----
__global__ __launch_bounds__(256) void head_kernel(
    const float* __restrict__ seq, const float* __restrict__ Wp,
    const float* __restrict__ bp,  const float* __restrict__ Wv,
    const float* __restrict__ bv,  float* __restrict__ out)
{
    int row  = blockIdx.x * (blockDim.x >> 5) + (threadIdx.x >> 5);
    int lane = threadIdx.x & 31;
    if (row >= T_) return;
    const float* h = seq + (size_t)row * H_;

    const float* wcol = (lane < 18) ? (Wp + lane) : Wv;
    const int stride  = (lane < 18) ? A_ : 1;
    float acc = 0.f;
    if (lane < 19) {
#pragma unroll 8
        for (int k = 0; k < H_; k++)
            acc = fmaf(__ldg(h + k), __ldg(wcol + k * stride), acc);
    }

    const float NEG_INF = __int_as_float(0xff800000);
    float logit = (lane < 18) ? acc + bp[lane] : NEG_INF;
    float m = logit;
#pragma unroll
    for (int off = 16; off; off >>= 1)
        m = fmaxf(m, __shfl_xor_sync(0xffffffffu, m, off));
    float e = (lane < 18) ? __expf(logit - m) : 0.f;
    float s = e;
#pragma unroll
    for (int off = 16; off; off >>= 1)
        s += __shfl_xor_sync(0xffffffffu, s, off);

    if (lane < 18)  out[(size_t)row * A_ + lane] = e / s;
    if (lane == 18) out[(size_t)T_ * A_ + row]   = acc + bv[0];
}

// ---------------- launch --------------------------------------------------
extern "C" void kernel_launch(void* const* d_in, const int* in_sizes, int n_in,
                              void* d_out, int out_size)
{
    (void)in_sizes; (void)n_in; (void)out_size;
    const float* x  = (const float*)d_in[0];
    const float* h0 = (const float*)d_in[1];
    const float* W1 = (const float*)d_in[2];
    const float* b1 = (const float*)d_in[3];
    const float* W2 = (const float*)d_in[4];
    const float* b2 = (const float*)d_in[5];
    const float* Wg = (const float*)d_in[6];
    const float* Ug = (const float*)d_in[7];
    const float* bg = (const float*)d_in[8];
    const float* Wp = (const float*)d_in[9];
    const float* bp = (const float*)d_in[10];
    const float* Wv = (const float*)d_in[11];
    const float* bv = (const float*)d_in[12];
    float* out = (float*)d_out;

    float *z1p, *z2p, *Xp, *seqp;
    cudaGetSymbolAddress((void**)&z1p,  g_z1);
    cudaGetSymbolAddress((void**)&z2p,  g_z2);
    cudaGetSymbolAddress((void**)&Xp,   g_X);
    cudaGetSymbolAddress((void**)&seqp, g_seq);

    init_kernel<<<2, 256>>>(h0);
    gemm_kernel<<<dim3(D_ / 64,  T_ / 64), 256>>>(x,   W1, b1, z1p, T_, D_,  DIN, 1);
    gemm_kernel<<<dim3(D_ / 64,  T_ / 64), 256>>>(z1p, W2, b2, z2p, T_, D_,  D_,  1);
    gemm_kernel<<<dim3(H3_ / 64, T_ / 64), 256>>>(z2p, Wg, bg, Xp,  T_, H3_, D_,  0);
    recur_kernel<<<NC, 256>>>(Ug, bg + H3_, Xp, seqp, out + (size_t)T_ * A_ + T_);
    head_kernel<<<T_ / 8, 256>>>(seqp, Wp, bp, Wv, bv, out);
}

// round 3
// speedup vs baseline: 1.1479x; 1.1479x over previous
#include <cuda_runtime.h>
#include <math.h>

#define T_   8192
#define DIN  2048
#define D_   512
#define H_   512
#define H3_  1536
#define A_   18

#define NC   64          // recurrence CTAs (single wave: 64 < 148 SMs)
#define HC   (H_/NC)     // 8 hidden units per CTA (one warp each)

// ---------------- scratch (device globals: no allocation allowed) ----------
__device__ float g_z1[(size_t)T_ * D_];          // 16 MB
__device__ float g_z2[(size_t)T_ * D_];          // 16 MB
__device__ float g_X [(size_t)T_ * H3_];         // 48 MB
__device__ float g_seq[(size_t)T_ * H_];         // 16 MB
__device__ unsigned long long g_hbuf[2 * H_];    // tagged double-buffered h

// ---------------- relaxed gpu-scope 64-bit ld/st for the spin protocol -----
__device__ __forceinline__ unsigned long long ld_relaxed_u64(const unsigned long long* p) {
    unsigned long long v;
    asm volatile("ld.relaxed.gpu.global.u64 %0, [%1];" : "=l"(v) : "l"(p) : "memory");
    return v;
}
__device__ __forceinline__ void st_relaxed_u64(unsigned long long* p, unsigned long long v) {
    asm volatile("st.relaxed.gpu.global.u64 [%0], %1;" :: "l"(p), "l"(v) : "memory");
}

// ---------------- fp32 tiled GEMM: C = act(A[M,K] @ B[K,N] + bias) ---------
// doInit: block (0,0) additionally resets the tagged h double-buffer (folds the
// init launch away so recur_kernel lands in ncu's profiled launch slot).
__global__ __launch_bounds__(256) void gemm_kernel(
    const float* __restrict__ A, const float* __restrict__ B,
    const float* __restrict__ bias, float* __restrict__ C,
    int M, int N, int K, int doRelu,
    const float* __restrict__ h0, int doInit)
{
    __shared__ float As[16][64];
    __shared__ float Bs[16][64];
    const int tid = threadIdx.x;

    if (doInit && blockIdx.x == 0 && blockIdx.y == 0) {
        // 256 threads cover 512 entries
        int i0 = tid, i1 = tid + 256;
        g_hbuf[i0] = 0xFFFFFFFFull;                                   // sentinel
        g_hbuf[i1] = 0xFFFFFFFFull;
        g_hbuf[H_ + i0] = ((unsigned long long)__float_as_uint(h0[i0]) << 32); // tag 0
        g_hbuf[H_ + i1] = ((unsigned long long)__float_as_uint(h0[i1]) << 32);
    }

    const int bm = blockIdx.y * 64;
    const int bn = blockIdx.x * 64;
    const int tx = tid & 15, ty = tid >> 4;

    const int aRow = tid >> 2;            // 0..63
    const int aK   = (tid & 3) << 2;      // 0,4,8,12
    const int bRow = tid >> 4;            // 0..15
    const int bCol = (tid & 15) << 2;     // 0..60

    const float* Aptr = A + (size_t)(bm + aRow) * K + aK;
    const float* Bptr = B + (size_t)bRow * N + bn + bCol;

    float acc[4][4];
#pragma unroll
    for (int i = 0; i < 4; i++)
#pragma unroll
        for (int j = 0; j < 4; j++) acc[i][j] = 0.f;

    for (int k0 = 0; k0 < K; k0 += 16) {
        float4 a4 = *(const float4*)(Aptr + k0);
        float4 b4 = *(const float4*)(Bptr + (size_t)k0 * N);
        As[aK + 0][aRow] = a4.x;
        As[aK + 1][aRow] = a4.y;
        As[aK + 2][aRow] = a4.z;
        As[aK + 3][aRow] = a4.w;
        *(float4*)&Bs[bRow][bCol] = b4;
        __syncthreads();
#pragma unroll
        for (int k = 0; k < 16; k++) {
            float4 av = *(const float4*)&As[k][ty << 2];
            float4 bv = *(const float4*)&Bs[k][tx << 2];
            float a_[4] = {av.x, av.y, av.z, av.w};
            float b_[4] = {bv.x, bv.y, bv.z, bv.w};
#pragma unroll
            for (int i = 0; i < 4; i++)
#pragma unroll
                for (int j = 0; j < 4; j++)
                    acc[i][j] = fmaf(a_[i], b_[j], acc[i][j]);
        }
        __syncthreads();
    }

#pragma unroll
    for (int i = 0; i < 4; i++) {
        int m = bm + (ty << 2) + i;
#pragma unroll
        for (int j = 0; j < 4; j++) {
            int n = bn + (tx << 2) + j;
            float v = acc[i][j] + bias[n];
            if (doRelu) v = fmaxf(v, 0.f);
            C[(size_t)m * N + n] = v;
        }
    }
}

// ---------------- GRU recurrence: 64 persistent CTAs ------------------------
// Warp-specialized sync: ONLY warp 0 spins on the tagged h words (<=32 loads in
// flight per SM, so the critical STG / poll load never queue behind hundreds of
// junk spin wavefronts in the per-SM L1tex FIFO). It stages h_{t-1} to shared
// and releases warps 1..7 via one __syncthreads. Producers write their own 8
// values straight to shared (poll warp skips them -> no self L2 round trip).
__global__ __launch_bounds__(256) void recur_kernel(
    const float* __restrict__ Ug,    // [H, 3H] row-major
    const float* __restrict__ brec,  // [3H]  (bg row 1)
    const float* __restrict__ X,     // [T, 3H]
    float* __restrict__ seq,         // [T, H]
    float* __restrict__ hT_out)      // [H]
{
    __shared__ float sh[2][H_];
    const int tid  = threadIdx.x;
    const int lane = tid & 31;
    const int w    = tid >> 5;                 // warp 0..7
    const int j    = blockIdx.x * HC + w;      // hidden unit owned by this warp

    // Stage this warp's Ug columns into registers: lane covers k = lane+32*kk
    float wz[16], wr[16], wh[16];
#pragma unroll
    for (int kk = 0; kk < 16; kk++) {
        const float* row = Ug + (size_t)(lane + (kk << 5)) * H3_;
        wz[kk] = row[j];
        wr[kk] = row[j + H_];
        wh[kk] = row[j + 2 * H_];
    }
    const float bz = brec[j], br = brec[j + H_], bh = brec[j + 2 * H_];

    // lane 0 holds the X row values for this unit (prefetched)
    float xz = 0.f, xr = 0.f, xh = 0.f;
    if (lane == 0) { xz = X[j]; xr = X[j + H_]; xh = X[j + 2 * H_]; }

    // poll warp: lane handles elements e = lane + 32*i, skipping own CTA's 8
    unsigned ownMask = 0;   // bits i where (lane + 32*i) is owned by this CTA
    {
        int base = blockIdx.x * HC;          // own units base..base+7
#pragma unroll
        for (int i = 0; i < 16; i++) {
            int e = lane + (i << 5);
            if (e >= base && e < base + HC) ownMask |= (1u << i);
        }
    }

    // seed shared for t=0 reads of h_{-1}: handled by poll warp at t=0 (tag 0
    // lives in g_hbuf[H_..] incl. own CTA's slots), so do NOT skip own at t=0.

    for (int t = 0; t < T_; t++) {
        const int p = t & 1;
        const unsigned tag = (unsigned)t;

        if (w == 0) {
            const unsigned long long* rb = g_hbuf + (((t - 1) & 1) ? H_ : 0);
            unsigned pend = 0xFFFFu;
            if (t > 0) pend &= ~ownMask;      // own values already staged
            unsigned long long v[16];
            while (pend) {
                unsigned np = pend;
#pragma unroll
                for (int i = 0; i < 16; i++) {
                    if (pend & (1u << i)) {
                        unsigned long long x = ld_relaxed_u64(rb + lane + (i << 5));
                        if ((unsigned)x == tag) { v[i] = x; np &= ~(1u << i); }
                    }
                }
                pend = np;
            }
            unsigned todo = 0xFFFFu;
            if (t > 0) todo &= ~ownMask;
#pragma unroll
            for (int i = 0; i < 16; i++)
                if (todo & (1u << i))
                    sh[p][lane + (i << 5)] = __uint_as_float((unsigned)(v[i] >> 32));
        }
        __syncthreads();

        // rec dot products: 3 gates, 16 k's per lane (2 accumulators per gate)
        float az0 = 0.f, ar0 = 0.f, ah0 = 0.f;
        float az1 = 0.f, ar1 = 0.f, ah1 = 0.f;
#pragma unroll
        for (int kk = 0; kk < 16; kk += 2) {
            float h0v = sh[p][lane + (kk << 5)];
            float h1v = sh[p][lane + ((kk + 1) << 5)];
            az0 = fmaf(h0v, wz[kk], az0);   az1 = fmaf(h1v, wz[kk + 1], az1);
            ar0 = fmaf(h0v, wr[kk], ar0);   ar1 = fmaf(h1v, wr[kk + 1], ar1);
            ah0 = fmaf(h0v, wh[kk], ah0);   ah1 = fmaf(h1v, wh[kk + 1], ah1);
        }
        float az = az0 + az1, ar = ar0 + ar1, ah = ah0 + ah1;
#pragma unroll
        for (int off = 16; off; off >>= 1) {
            az += __shfl_xor_sync(0xffffffffu, az, off);
            ar += __shfl_xor_sync(0xffffffffu, ar, off);
            ah += __shfl_xor_sync(0xffffffffu, ah, off);
        }

        if (lane == 0) {
            float zt = __fdividef(1.f, 1.f + __expf(-(xz + az + bz)));
            float rt = __fdividef(1.f, 1.f + __expf(-(xr + ar + br)));
            float hh = __fdividef(1.f, 1.f + __expf(-(xh + rt * (ah + bh))));
            float hp = sh[p][j];
            float hn = fmaf(zt, hp - hh, hh);   // zt*hp + (1-zt)*hh
            seq[(size_t)t * H_ + j] = hn;
            // stage own value locally for next step (poll warp skips it)
            sh[p ^ 1][j] = hn;
            unsigned long long pk =
                ((unsigned long long)__float_as_uint(hn) << 32) | (unsigned)(t + 1);
            st_relaxed_u64(g_hbuf + (p ? H_ : 0) + j, pk);
            if (t == T_ - 1) hT_out[j] = hn;
            if (t + 1 < T_) {   // prefetch next X row
                const float* xp = X + (size_t)(t + 1) * H3_;
                xz = __ldg(xp + j); xr = __ldg(xp + j + H_); xh = __ldg(xp + j + 2 * H_);
            }
        }
        // single barrier per step: sh is parity double-buffered; producers write
        // sh[p^1] (disjoint from sh[p] readers), reads of sh[p^1] gated by the
        // next iteration's __syncthreads.
    }
}

// ---------------- heads: softmax policy (18) + value, one warp per row -----
__global__ __launch_bounds__(256) void head_kernel(
    const float* __restrict__ seq, const float* __restrict__ Wp,
    const float* __restrict__ bp,  const float* __restrict__ Wv,
    const float* __restrict__ bv,  float* __restrict__ out)
{
    int row  = blockIdx.x * (blockDim.x >> 5) + (threadIdx.x >> 5);
    int lane = threadIdx.x & 31;
    if (row >= T_) return;
    const float* h = seq + (size_t)row * H_;

    const float* wcol = (lane < 18) ? (Wp + lane) : Wv;
    const int stride  = (lane < 18) ? A_ : 1;
    float acc = 0.f;
    if (lane < 19) {
#pragma unroll 8
        for (int k = 0; k < H_; k++)
            acc = fmaf(__ldg(h + k), __ldg(wcol + k * stride), acc);
    }

    const float NEG_INF = __int_as_float(0xff800000);
    float logit = (lane < 18) ? acc + bp[lane] : NEG_INF;
    float m = logit;
#pragma unroll
    for (int off = 16; off; off >>= 1)
        m = fmaxf(m, __shfl_xor_sync(0xffffffffu, m, off));
    float e = (lane < 18) ? __expf(logit - m) : 0.f;
    float s = e;
#pragma unroll
    for (int off = 16; off; off >>= 1)
        s += __shfl_xor_sync(0xffffffffu, s, off);

    if (lane < 18)  out[(size_t)row * A_ + lane] = e / s;
    if (lane == 18) out[(size_t)T_ * A_ + row]   = acc + bv[0];
}

// ---------------- launch --------------------------------------------------
extern "C" void kernel_launch(void* const* d_in, const int* in_sizes, int n_in,
                              void* d_out, int out_size)
{
    (void)in_sizes; (void)n_in; (void)out_size;
    const float* x  = (const float*)d_in[0];
    const float* h0 = (const float*)d_in[1];
    const float* W1 = (const float*)d_in[2];
    const float* b1 = (const float*)d_in[3];
    const float* W2 = (const float*)d_in[4];
    const float* b2 = (const float*)d_in[5];
    const float* Wg = (const float*)d_in[6];
    const float* Ug = (const float*)d_in[7];
    const float* bg = (const float*)d_in[8];
    const float* Wp = (const float*)d_in[9];
    const float* bp = (const float*)d_in[10];
    const float* Wv = (const float*)d_in[11];
    const float* bv = (const float*)d_in[12];
    float* out = (float*)d_out;

    float *z1p, *z2p, *Xp, *seqp;
    cudaGetSymbolAddress((void**)&z1p,  g_z1);
    cudaGetSymbolAddress((void**)&z2p,  g_z2);
    cudaGetSymbolAddress((void**)&Xp,   g_X);
    cudaGetSymbolAddress((void**)&seqp, g_seq);

    // init folded into gemm1 -> recur_kernel is process-launch slot that ncu
    // profiles (-s 5 -c 1) next round.
    gemm_kernel<<<dim3(D_ / 64,  T_ / 64), 256>>>(x,   W1, b1, z1p, T_, D_,  DIN, 1, h0, 1);
    gemm_kernel<<<dim3(D_ / 64,  T_ / 64), 256>>>(z1p, W2, b2, z2p, T_, D_,  D_,  1, h0, 0);
    gemm_kernel<<<dim3(H3_ / 64, T_ / 64), 256>>>(z2p, Wg, bg, Xp,  T_, H3_, D_,  0, h0, 0);
    recur_kernel<<<NC, 256>>>(Ug, bg + H3_, Xp, seqp, out + (size_t)T_ * A_ + T_);
    head_kernel<<<T_ / 8, 256>>>(seqp, Wp, bp, Wv, bv, out);
}